// round 2
// baseline (speedup 1.0000x reference)
#include <cuda_runtime.h>
#include <cstdint>

// ---------------- problem constants ----------------
#define B 32
#define NOISE 128
#define H 512
#define O 1024
#define HEADS 8
#define T 128
#define S 1024          // 2*H
#define G3 1536         // 3*H
#define NW 8192         // O*HEADS
#define NROWS 4096      // B*T
#define EOS 1023
#define SLOPE 0.2f
#define EPS_BN 1e-5f
#define EPS_COS 1e-8f

// ---------------- device scratch (static, no allocs) ----------------
__device__ __align__(16) float g_hT[H * B];       // [feat][batch]
__device__ __align__(16) float g_mT[H * B];
__device__ __align__(16) float g_zpartT[H * B];   // bn2-normalized z half
__device__ __align__(16) float g_pebnT[H * B];    // bn2-normalized pe half
__device__ __align__(16) float g_gizT[G3 * B];    // z_part @ Wih_right^T + b_ih
__device__ __align__(16) float g_gihT[G3 * B];
__device__ __align__(16) float g_ghhT[G3 * B];
__device__ __align__(16) float g_ghmT[G3 * B];
__device__ __align__(16) float g_gimem[T * G3];   // per-step broadcast gi for m path
__device__ __align__(16) float g_xhT[H * B];      // bn3(lrelu(h))
__device__ __align__(16) float g_xmT[H * B];
__device__ int g_prev[B];
__device__ __align__(16) float g_outs[NROWS * O]; // row = b*T + t
__device__ __align__(16) float g_mems[NROWS * O];
__device__ __align__(16) float g_P0[(size_t)NROWS * NW]; // lrelu(outs @ lin_w^T + b)
__device__ __align__(16) float g_P1[(size_t)NROWS * NW];

// ---------------- helpers ----------------
__device__ __forceinline__ float wsum(float v) {
#pragma unroll
    for (int o = 16; o > 0; o >>= 1) v += __shfl_xor_sync(0xffffffffu, v, o);
    return v;
}
__device__ __forceinline__ float lrelu(float x) { return x >= 0.f ? x : SLOPE * x; }
__device__ __forceinline__ float sigm(float x) { return 1.f / (1.f + expf(-x)); }

// ---------------- init: z path, bn1, bn2(z half), h/m/prev init ----------------
__global__ void k_init(const float* __restrict__ z, const float* __restrict__ w,
                       const float* __restrict__ wb,
                       const float* __restrict__ g1, const float* __restrict__ b1,
                       const float* __restrict__ g2, const float* __restrict__ b2) {
    int j = blockIdx.x;        // 0..511 (one warp per column)
    int b = threadIdx.x;       // lane = batch
    const float* wr = w + (size_t)j * NOISE;
    const float* zr = z + (size_t)b * NOISE;
    float acc = wb[j];
#pragma unroll 8
    for (int k = 0; k < NOISE; k++) acc += zr[k] * wr[k];
    float v = lrelu(acc);
    // bn1 over batch (one warp)
    float mu = wsum(v) * (1.f / B);
    float m2 = wsum(v * v) * (1.f / B);
    float var = fmaxf(m2 - mu * mu, 0.f);
    float z0 = (v - mu) * rsqrtf(var + EPS_BN) * g1[j] + b1[j];
    // bn2 on z half (columns H+j of concat)
    float mu2 = wsum(z0) * (1.f / B);
    float q2 = wsum(z0 * z0) * (1.f / B);
    float var2 = fmaxf(q2 - mu2 * mu2, 0.f);
    float zp = (z0 - mu2) * rsqrtf(var2 + EPS_BN) * g2[H + j] + b2[H + j];
    g_hT[j * B + b] = z0;
    g_mT[j * B + b] = z0;
    g_zpartT[j * B + b] = zp;
    if (j == 0) g_prev[b] = EOS;
}

// ---------------- gi_z = z_part @ w_ih[:,H:]^T + b_ih (once) ----------------
__global__ void k_giz(const float* __restrict__ w_ih, const float* __restrict__ b_ih) {
    int c = blockIdx.x;        // 0..1535
    int b = threadIdx.x;
    const float* wr = w_ih + (size_t)c * S + H;
    float a0 = b_ih[c], a1 = 0.f, a2 = 0.f, a3 = 0.f;
#pragma unroll 16
    for (int k = 0; k < H; k += 4) {
        float4 wv = *reinterpret_cast<const float4*>(wr + k);
        a0 += g_zpartT[(k + 0) * B + b] * wv.x;
        a1 += g_zpartT[(k + 1) * B + b] * wv.y;
        a2 += g_zpartT[(k + 2) * B + b] * wv.z;
        a3 += g_zpartT[(k + 3) * B + b] * wv.w;
    }
    g_gizT[c * B + b] = (a0 + a1) + (a2 + a3);
}

// ---------------- gi_mem[t] = xs[t] @ w_ih^T + b_ih for all t (once) ----------------
__global__ void k_gimem(const float* __restrict__ memory, const int* __restrict__ perm,
                        const float* __restrict__ w_ih, const float* __restrict__ b_ih) {
    __shared__ __align__(16) float xs[S];
    int t = blockIdx.y;
    int p = perm[t];
    for (int i = threadIdx.x; i < S; i += blockDim.x) xs[i] = memory[(size_t)p * S + i];
    __syncthreads();
    int ws = threadIdx.x >> 5, lane = threadIdx.x & 31;
    int c = blockIdx.x * 16 + ws;   // gridDim.x = 96 -> 1536 columns
    const float* wr = w_ih + (size_t)c * S;
    float partial = 0.f;
#pragma unroll 8
    for (int k = lane; k < S; k += 32) partial += xs[k] * wr[k];
    partial = wsum(partial);
    if (lane == 0) g_gimem[t * G3 + c] = partial + b_ih[c];
}

// ---------------- per step: pe = bn2(lrelu(emb[prev])) ----------------
__global__ void k_pe(const float* __restrict__ emb, const float* __restrict__ g2,
                     const float* __restrict__ b2) {
    int j = blockIdx.x;        // 0..511
    int b = threadIdx.x;
    int idx = g_prev[b];
    float v = lrelu(emb[(size_t)idx * H + j]);
    float mu = wsum(v) * (1.f / B);
    float m2 = wsum(v * v) * (1.f / B);
    float var = fmaxf(m2 - mu * mu, 0.f);
    g_pebnT[j * B + b] = (v - mu) * rsqrtf(var + EPS_BN) * g2[j] + b2[j];
}

// ---------------- per step: gate GEMMs (gi_h, gh_h, gh_m) ----------------
__global__ void k_gates(const float* __restrict__ w_ih, const float* __restrict__ w_hh,
                        const float* __restrict__ b_hh) {
    int id = blockIdx.x;       // 0..4607
    int b = threadIdx.x;
    int which = id / G3;
    int c = id - which * G3;
    const float* in;
    const float* wr;
    float a0, a1 = 0.f, a2 = 0.f, a3 = 0.f;
    float* out;
    if (which == 0) {
        in = g_pebnT; wr = w_ih + (size_t)c * S;       // pe half: cols 0..H-1
        a0 = g_gizT[c * B + b]; out = g_gihT;
    } else if (which == 1) {
        in = g_hT; wr = w_hh + (size_t)c * H;
        a0 = b_hh[c]; out = g_ghhT;
    } else {
        in = g_mT; wr = w_hh + (size_t)c * H;
        a0 = b_hh[c]; out = g_ghmT;
    }
#pragma unroll 16
    for (int k = 0; k < H; k += 4) {
        float4 wv = *reinterpret_cast<const float4*>(wr + k);
        a0 += in[(k + 0) * B + b] * wv.x;
        a1 += in[(k + 1) * B + b] * wv.y;
        a2 += in[(k + 2) * B + b] * wv.z;
        a3 += in[(k + 3) * B + b] * wv.w;
    }
    out[c * B + b] = (a0 + a1) + (a2 + a3);
}

// ---------------- per step: GRU combine + bn3(lrelu(state)) ----------------
__global__ void k_gru(int t, const float* __restrict__ g3, const float* __restrict__ b3) {
    int id = blockIdx.x;       // 0..1023
    int path = id >> 9;
    int j = id & 511;
    int b = threadIdx.x;
    float gr, gz, gn, hr, hz, hn, hprev;
    if (path == 0) {
        gr = g_gihT[j * B + b]; gz = g_gihT[(H + j) * B + b]; gn = g_gihT[(2 * H + j) * B + b];
        hr = g_ghhT[j * B + b]; hz = g_ghhT[(H + j) * B + b]; hn = g_ghhT[(2 * H + j) * B + b];
        hprev = g_hT[j * B + b];
    } else {
        const float* gm = g_gimem + t * G3;
        gr = gm[j]; gz = gm[H + j]; gn = gm[2 * H + j];
        hr = g_ghmT[j * B + b]; hz = g_ghmT[(H + j) * B + b]; hn = g_ghmT[(2 * H + j) * B + b];
        hprev = g_mT[j * B + b];
    }
    float r = sigm(gr + hr);
    float zt = sigm(gz + hz);
    float n = tanhf(gn + r * hn);
    float hnew = (1.f - zt) * n + zt * hprev;
    (path ? g_mT : g_hT)[j * B + b] = hnew;
    float v = lrelu(hnew);
    float mu = wsum(v) * (1.f / B);
    float m2 = wsum(v * v) * (1.f / B);
    float var = fmaxf(m2 - mu * mu, 0.f);
    (path ? g_xmT : g_xhT)[j * B + b] = (v - mu) * rsqrtf(var + EPS_BN) * g3[j] + b3[j];
}

// ---------------- per step: logits, softmax, argmax, store ----------------
__global__ void k_logits(int t, const float* __restrict__ h2o_w,
                         const float* __restrict__ h2o_b) {
    __shared__ __align__(16) float xs[H];
    __shared__ float red[256];
    __shared__ int redi[256];
    int bid = blockIdx.x;      // 0..63 : path*32 + b
    int path = bid >> 5;
    int b = bid & 31;
    int tid = threadIdx.x;
    const float* xT = path ? g_xmT : g_xhT;
    for (int i = tid; i < H; i += 256) xs[i] = xT[i * B + b];
    __syncthreads();

    float lv[4];
    float localmax = -1e30f;
    int localidx = 0;
#pragma unroll
    for (int i = 0; i < 4; i++) {
        int o = tid + i * 256;
        const float* wr = h2o_w + (size_t)o * H;
        float a0 = h2o_b[o], a1 = 0.f, a2 = 0.f, a3 = 0.f;
#pragma unroll 8
        for (int k = 0; k < H; k += 4) {
            float4 wv = *reinterpret_cast<const float4*>(wr + k);
            float4 xv = *reinterpret_cast<const float4*>(xs + k);
            a0 += xv.x * wv.x; a1 += xv.y * wv.y; a2 += xv.z * wv.z; a3 += xv.w * wv.w;
        }
        float acc = (a0 + a1) + (a2 + a3);
        lv[i] = acc;
        if (acc > localmax) { localmax = acc; localidx = o; }
    }
    red[tid] = localmax; redi[tid] = localidx;
    __syncthreads();
    for (int s2 = 128; s2 > 0; s2 >>= 1) {
        if (tid < s2) {
            float ov = red[tid + s2]; int oi = redi[tid + s2];
            if (ov > red[tid] || (ov == red[tid] && oi < redi[tid])) { red[tid] = ov; redi[tid] = oi; }
        }
        __syncthreads();
    }
    float maxv = red[0];
    int amax = redi[0];
    __syncthreads();

    float ev[4], esum = 0.f;
#pragma unroll
    for (int i = 0; i < 4; i++) { ev[i] = expf(lv[i] - maxv); esum += ev[i]; }
    red[tid] = esum;
    __syncthreads();
    for (int s2 = 128; s2 > 0; s2 >>= 1) {
        if (tid < s2) red[tid] += red[tid + s2];
        __syncthreads();
    }
    float inv = 1.f / red[0];
    float* dst = (path ? g_mems : g_outs) + (size_t)(b * T + t) * O;
#pragma unroll
    for (int i = 0; i < 4; i++) dst[tid + i * 256] = ev[i] * inv;
    if (path == 0 && tid == 0) g_prev[b] = amax;
}

// ---------------- projection GEMM: P = lrelu(Y @ lin_w^T + lin_b) ----------------
__global__ void k_proj(const float* __restrict__ lin_w, const float* __restrict__ lin_b) {
    __shared__ __align__(16) float As[8][128];
    __shared__ __align__(16) float Bs[8][128];
    const float* Y = blockIdx.z ? g_mems : g_outs;
    float* P = blockIdx.z ? g_P1 : g_P0;

    int tid = threadIdx.x;
    int tx = tid & 15, ty = tid >> 4;
    int ar = tid >> 1, ac = (tid & 1) << 2;

    const float* Arow = Y + (size_t)(blockIdx.y * 128 + ar) * O + ac;
    const float* Brow = lin_w + (size_t)(blockIdx.x * 128 + ar) * O + ac;

    float acc[8][8];
#pragma unroll
    for (int i = 0; i < 8; i++)
#pragma unroll
        for (int j = 0; j < 8; j++) acc[i][j] = 0.f;

    for (int k0 = 0; k0 < O; k0 += 8) {
        float4 av = *reinterpret_cast<const float4*>(Arow + k0);
        float4 bv = *reinterpret_cast<const float4*>(Brow + k0);
        __syncthreads();
        As[ac + 0][ar] = av.x; As[ac + 1][ar] = av.y; As[ac + 2][ar] = av.z; As[ac + 3][ar] = av.w;
        Bs[ac + 0][ar] = bv.x; Bs[ac + 1][ar] = bv.y; Bs[ac + 2][ar] = bv.z; Bs[ac + 3][ar] = bv.w;
        __syncthreads();
#pragma unroll
        for (int kk = 0; kk < 8; kk++) {
            float4 a0 = *reinterpret_cast<const float4*>(&As[kk][ty * 4]);
            float4 a1 = *reinterpret_cast<const float4*>(&As[kk][64 + ty * 4]);
            float4 b0 = *reinterpret_cast<const float4*>(&Bs[kk][tx * 4]);
            float4 b1 = *reinterpret_cast<const float4*>(&Bs[kk][64 + tx * 4]);
            float a[8] = {a0.x, a0.y, a0.z, a0.w, a1.x, a1.y, a1.z, a1.w};
            float bb[8] = {b0.x, b0.y, b0.z, b0.w, b1.x, b1.y, b1.z, b1.w};
#pragma unroll
            for (int i = 0; i < 8; i++)
#pragma unroll
                for (int j = 0; j < 8; j++) acc[i][j] += a[i] * bb[j];
        }
    }

    int n0 = blockIdx.x * 128 + tx * 4;
    int n1 = n0 + 64;
#pragma unroll
    for (int i = 0; i < 8; i++) {
        int mloc = (i < 4) ? (ty * 4 + i) : (64 + ty * 4 + i - 4);
        size_t mrow = (size_t)(blockIdx.y * 128 + mloc) * NW;
        float4 v0, v1;
        v0.x = lrelu(acc[i][0] + lin_b[n0 + 0]);
        v0.y = lrelu(acc[i][1] + lin_b[n0 + 1]);
        v0.z = lrelu(acc[i][2] + lin_b[n0 + 2]);
        v0.w = lrelu(acc[i][3] + lin_b[n0 + 3]);
        v1.x = lrelu(acc[i][4] + lin_b[n1 + 0]);
        v1.y = lrelu(acc[i][5] + lin_b[n1 + 1]);
        v1.z = lrelu(acc[i][6] + lin_b[n1 + 2]);
        v1.w = lrelu(acc[i][7] + lin_b[n1 + 3]);
        *reinterpret_cast<float4*>(&P[mrow + n0]) = v0;
        *reinterpret_cast<float4*>(&P[mrow + n1]) = v1;
    }
}

// ---------------- cosine similarity over HEADS ----------------
__global__ void k_cossim(float* __restrict__ out) {
    int gid = blockIdx.x * 256 + threadIdx.x;   // 0 .. NROWS*O-1
    int row = gid >> 10;
    int o = gid & 1023;
    const float* a = g_P0 + (size_t)row * NW + o * HEADS;
    const float* bq = g_P1 + (size_t)row * NW + o * HEADS;
    float4 a0 = *reinterpret_cast<const float4*>(a);
    float4 a1 = *reinterpret_cast<const float4*>(a + 4);
    float4 b0 = *reinterpret_cast<const float4*>(bq);
    float4 b1 = *reinterpret_cast<const float4*>(bq + 4);
    float dot = a0.x * b0.x + a0.y * b0.y + a0.z * b0.z + a0.w * b0.w
              + a1.x * b1.x + a1.y * b1.y + a1.z * b1.z + a1.w * b1.w;
    float na2 = a0.x * a0.x + a0.y * a0.y + a0.z * a0.z + a0.w * a0.w
              + a1.x * a1.x + a1.y * a1.y + a1.z * a1.z + a1.w * a1.w;
    float nb2 = b0.x * b0.x + b0.y * b0.y + b0.z * b0.z + b0.w * b0.w
              + b1.x * b1.x + b1.y * b1.y + b1.z * b1.z + b1.w * b1.w;
    float denom = fmaxf(sqrtf(na2) * sqrtf(nb2), EPS_COS);
    out[gid] = dot / denom;
}

// ---------------- host launcher (graph-capturable, no allocs/syncs) ----------------
extern "C" void kernel_launch(void* const* d_in, const int* in_sizes, int n_in,
                              void* d_out, int out_size) {
    const float* z      = (const float*)d_in[0];
    const float* z2h_w  = (const float*)d_in[1];
    const float* z2h_b  = (const float*)d_in[2];
    const float* bn1_g  = (const float*)d_in[3];
    const float* bn1_b  = (const float*)d_in[4];
    const float* emb    = (const float*)d_in[5];
    const float* bn2_g  = (const float*)d_in[6];
    const float* bn2_b  = (const float*)d_in[7];
    const float* w_ih   = (const float*)d_in[8];
    const float* w_hh   = (const float*)d_in[9];
    const float* b_ih   = (const float*)d_in[10];
    const float* b_hh   = (const float*)d_in[11];
    const float* h2o_w  = (const float*)d_in[12];
    const float* h2o_b  = (const float*)d_in[13];
    const float* bn3_g  = (const float*)d_in[14];
    const float* bn3_b  = (const float*)d_in[15];
    const float* lin_w  = (const float*)d_in[16];
    const float* lin_b  = (const float*)d_in[17];
    const float* memory = (const float*)d_in[18];
    const int*   perm   = (const int*)d_in[19];
    // d_in[20] = num_steps (=128), d_in[21] = temperature (unused) — shapes are fixed.

    k_init<<<H, B>>>(z, z2h_w, z2h_b, bn1_g, bn1_b, bn2_g, bn2_b);
    k_giz<<<G3, B>>>(w_ih, b_ih);
    k_gimem<<<dim3(96, T), 512>>>(memory, perm, w_ih, b_ih);

    for (int t = 0; t < T; t++) {
        k_pe<<<H, B>>>(emb, bn2_g, bn2_b);
        k_gates<<<3 * G3, B>>>(w_ih, w_hh, b_hh);
        k_gru<<<2 * H, B>>>(t, bn3_g, bn3_b);
        k_logits<<<64, 256>>>(t, h2o_w, h2o_b);
    }

    k_proj<<<dim3(NW / 128, NROWS / 128, 2), 256>>>(lin_w, lin_b);
    k_cossim<<<(NROWS * O) / 256, 256>>>((float*)d_out);
}